// round 5
// baseline (speedup 1.0000x reference)
#include <cuda_runtime.h>
#include <math.h>

// Problem shape (fixed by dataset): N=100000, H=32, K=15, C_in=C_out=64
#define MAXN 100000
#define NB_H 32
#define KPTS 15
#define CH   64

// Scratch (__device__ globals: allocation-free rule)
__device__ float4 g_pts4[MAXN];     // s_pts packed as float4 (w unused)
__device__ float  g_val[MAXN * CH]; // raw kpconv rows for flagged points
__device__ int    g_flag[MAXN];     // 1 if candidate row
__device__ float  g_sum[CH];
__device__ float  g_sumsq[CH];
__device__ float  g_thresh;         // squared candidate radius

static __host__ __device__ __forceinline__ float kp_extent() {
    return (float)(0.1 * 1.2 / 2.5);
}

// ---------------- init: pack s_pts, zero flags/sums, compute threshold ----------------
__global__ void __launch_bounds__(256) init_kernel(const float* __restrict__ s_pts,
                                                   const float* __restrict__ kp, int N)
{
    const int i = blockIdx.x * 256 + threadIdx.x;
    if (i < N) {
        g_flag[i] = 0;
        g_pts4[i] = make_float4(__ldg(s_pts + 3*i), __ldg(s_pts + 3*i + 1),
                                __ldg(s_pts + 3*i + 2), 0.0f);
    }
    if (i < CH) { g_sum[i] = 0.0f; g_sumsq[i] = 0.0f; }
    if (i == 0) {
        float mx = 0.0f;
        for (int k = 0; k < KPTS; k++) {
            const float a = kp[3*k], b = kp[3*k+1], c = kp[3*k+2];
            mx = fmaxf(mx, sqrtf(a*a + b*b + c*c));
        }
        const float t = (kp_extent() + mx) * 1.0002f + 1e-6f;  // false positives ok
        g_thresh = t * t;
    }
}

// ---------------- detect: lean, no smem; 4 pairs/thread; flag candidates ----------------
__global__ void __launch_bounds__(256) detect_kernel(
    const int* __restrict__ inds, const float* __restrict__ q_pts, int N)
{
    const int t = blockIdx.x * 256 + threadIdx.x;   // quad id: covers inds[4t .. 4t+3]
    const int n = t >> 3;                           // 8 threads per point (H=32)
    if (n >= N) return;

    // q loads: 8 threads per point, 4 points per warp -> few lines, broadcast-friendly
    const float qx = __ldg(q_pts + 3*n);
    const float qy = __ldg(q_pts + 3*n + 1);
    const float qz = __ldg(q_pts + 3*n + 2);
    const float thr = g_thresh;

    const int4 iv = __ldg(reinterpret_cast<const int4*>(inds) + t);

    // 4 independent gathers in flight (MLP=4)
    bool any = false;
    {
        const int id = iv.x;
        if ((unsigned)id < (unsigned)N) {
            const float4 p = __ldg(&g_pts4[id]);
            const float dx = p.x - qx, dy = p.y - qy, dz = p.z - qz;
            any |= (fmaf(dx, dx, fmaf(dy, dy, dz * dz)) < thr);
        }
    }
    {
        const int id = iv.y;
        if ((unsigned)id < (unsigned)N) {
            const float4 p = __ldg(&g_pts4[id]);
            const float dx = p.x - qx, dy = p.y - qy, dz = p.z - qz;
            any |= (fmaf(dx, dx, fmaf(dy, dy, dz * dz)) < thr);
        }
    }
    {
        const int id = iv.z;
        if ((unsigned)id < (unsigned)N) {
            const float4 p = __ldg(&g_pts4[id]);
            const float dx = p.x - qx, dy = p.y - qy, dz = p.z - qz;
            any |= (fmaf(dx, dx, fmaf(dy, dy, dz * dz)) < thr);
        }
    }
    {
        const int id = iv.w;
        if ((unsigned)id < (unsigned)N) {
            const float4 p = __ldg(&g_pts4[id]);
            const float dx = p.x - qx, dy = p.y - qy, dz = p.z - qz;
            any |= (fmaf(dx, dx, fmaf(dy, dy, dz * dz)) < thr);
        }
    }
    if (any) g_flag[n] = 1;   // racy same-value store: benign
}

// ---------------- heavy: scan flags, exact KPConv per flagged point ----------------
#define HEAVY_BLOCKS 32
__global__ void __launch_bounds__(256) heavy_kernel(
    const int*   __restrict__ inds,
    const float* __restrict__ q_pts,
    const float* __restrict__ x,
    const float* __restrict__ kp,
    const float* __restrict__ W,   // [K, C, C]
    int N)
{
    __shared__ float sw[8][KPTS][CH];   // 30 KB (fine: this kernel is tiny)
    const int warp = threadIdx.x >> 5;
    const int lane = threadIdx.x & 31;
    const unsigned FULL = 0xffffffffu;

    const float EXT  = kp_extent();
    const float EXT2 = EXT * EXT;
    const float INVE = 1.0f / EXT;
    const float thr  = g_thresh;

    float kx[KPTS], ky[KPTS], kz[KPTS];
#pragma unroll
    for (int k = 0; k < KPTS; k++) {
        kx[k] = __ldg(kp + 3*k);
        ky[k] = __ldg(kp + 3*k + 1);
        kz[k] = __ldg(kp + 3*k + 2);
    }

    const int ngrp = (N + 31) >> 5;                 // flag groups of 32
    const int wid_g = blockIdx.x * 8 + warp;
    for (int g = wid_g; g < ngrp; g += HEAVY_BLOCKS * 8) {
        const int fn = g * 32 + lane;
        const int f = (fn < N) ? g_flag[fn] : 0;
        unsigned hits = __ballot_sync(FULL, f != 0);

        while (hits) {
            const int bit = __ffs(hits) - 1;
            hits &= (hits - 1);
            const int n = g * 32 + bit;

            const float qx = __ldg(q_pts + 3*n);
            const float qy = __ldg(q_pts + 3*n + 1);
            const float qz = __ldg(q_pts + 3*n + 2);

            const int idx = __ldg(inds + n * NB_H + lane);
            const bool valid = ((unsigned)idx < (unsigned)N);
            float nx = 1e9f, ny = 1e9f, nz = 1e9f;
            if (valid) {
                const float4 p = __ldg(&g_pts4[idx]);
                nx = p.x - qx; ny = p.y - qy; nz = p.z - qz;
            }
            const float r2 = fmaf(nx, nx, fmaf(ny, ny, nz * nz));
            unsigned mask = __ballot_sync(FULL, valid && (r2 < thr));

            float acc0[KPTS], acc1[KPTS];
#pragma unroll
            for (int k = 0; k < KPTS; k++) { acc0[k] = 0.0f; acc1[k] = 0.0f; }

            unsigned m = mask;
            while (m) {
                const int hs = __ffs(m) - 1;
                m &= (m - 1);
                const int   sidx = __shfl_sync(FULL, idx, hs);
                const float bx = __shfl_sync(FULL, nx, hs);
                const float by = __shfl_sync(FULL, ny, hs);
                const float bz = __shfl_sync(FULL, nz, hs);
                const float xv0 = __ldg(x + (long)sidx * CH + lane);
                const float xv1 = __ldg(x + (long)sidx * CH + lane + 32);
#pragma unroll
                for (int k = 0; k < KPTS; k++) {
                    const float dx = bx - kx[k];
                    const float dy = by - ky[k];
                    const float dz = bz - kz[k];
                    const float d2 = fmaf(dx, dx, fmaf(dy, dy, dz * dz));
                    if (d2 < EXT2) {
                        const float w = fmaxf(1.0f - sqrtf(d2) * INVE, 0.0f);
                        acc0[k] = fmaf(w, xv0, acc0[k]);
                        acc1[k] = fmaf(w, xv1, acc1[k]);
                    }
                }
            }

            unsigned kmask = 0;
#pragma unroll
            for (int k = 0; k < KPTS; k++) {
                sw[warp][k][lane]      = acc0[k];
                sw[warp][k][lane + 32] = acc1[k];
                if (__ballot_sync(FULL, (acc0[k] != 0.0f) || (acc1[k] != 0.0f)))
                    kmask |= (1u << k);
            }
            __syncwarp();

            float o0 = 0.0f, o1 = 0.0f;
            for (int k = 0; k < KPTS; k++) {
                if (!(kmask & (1u << k))) continue;
                const float* Wk = W + (long)k * CH * CH;
#pragma unroll 8
                for (int c = 0; c < CH; c++) {
                    const float wv = sw[warp][k][c];
                    o0 = fmaf(wv, __ldg(Wk + c * CH + lane),      o0);
                    o1 = fmaf(wv, __ldg(Wk + c * CH + lane + 32), o1);
                }
            }
            __syncwarp();

            g_val[(long)n * CH + lane]      = o0;
            g_val[(long)n * CH + lane + 32] = o1;
            atomicAdd(&g_sum[lane],        o0);
            atomicAdd(&g_sum[lane + 32],   o1);
            atomicAdd(&g_sumsq[lane],      o0 * o0);
            atomicAdd(&g_sumsq[lane + 32], o1 * o1);
        }
    }
}

// ---------------- pass 3: per-block stats finalize + normalize/LeakyReLU stream ----------------
__global__ void __launch_bounds__(256) pass3_kernel(float* __restrict__ out, int N) {
    __shared__ float zz[CH], mm[CH], iv[CH];
    const int t = threadIdx.x;
    if (t < CH) {
        const float invN = 1.0f / (float)N;
        const float mean = g_sum[t] * invN;
        const float var  = fmaxf(g_sumsq[t] * invN - mean * mean, 0.0f);
        const float inv  = rsqrtf(var + 1e-5f);
        const float z    = (0.0f - mean) * inv;
        mm[t] = mean;
        iv[t] = inv;
        zz[t] = (z >= 0.0f) ? z : 0.1f * z;
    }
    __syncthreads();

    const int j = (t & 15) * 4;                 // 16 threads * float4 = 64 channels
    const int r0 = blockIdx.x * 32 + (t >> 4);  // 32 rows per block, 2 per thread

#pragma unroll
    for (int rr = 0; rr < 2; rr++) {
        const int r = r0 + rr * 16;
        if (r >= N) continue;
        float4 o;
        if (__ldg(&g_flag[r])) {
            const float4 v = *reinterpret_cast<const float4*>(g_val + (long)r * CH + j);
            float a = (v.x - mm[j])     * iv[j];
            float b = (v.y - mm[j + 1]) * iv[j + 1];
            float c = (v.z - mm[j + 2]) * iv[j + 2];
            float d = (v.w - mm[j + 3]) * iv[j + 3];
            o.x = (a >= 0.0f) ? a : 0.1f * a;
            o.y = (b >= 0.0f) ? b : 0.1f * b;
            o.z = (c >= 0.0f) ? c : 0.1f * c;
            o.w = (d >= 0.0f) ? d : 0.1f * d;
        } else {
            o = make_float4(zz[j], zz[j + 1], zz[j + 2], zz[j + 3]);
        }
        reinterpret_cast<float4*>(out)[(long)r * (CH / 4) + (t & 15)] = o;
    }
}

// ---------------- launch: 4 kernels ----------------
extern "C" void kernel_launch(void* const* d_in, const int* in_sizes, int n_in,
                              void* d_out, int out_size) {
    const float* q_pts = (const float*)d_in[0];
    const float* s_pts = (const float*)d_in[1];
    const int*   inds  = (const int*)  d_in[2];
    const float* x     = (const float*)d_in[3];
    const float* kp    = (const float*)d_in[4];
    const float* W     = (const float*)d_in[5];
    float* out = (float*)d_out;

    const int N = in_sizes[0] / 3;

    init_kernel<<<(N + 255) / 256, 256>>>(s_pts, kp, N);
    detect_kernel<<<(N * 8 + 255) / 256, 256>>>(inds, q_pts, N);
    heavy_kernel<<<HEAVY_BLOCKS, 256>>>(inds, q_pts, x, kp, W, N);
    pass3_kernel<<<(N + 31) / 32, 256>>>(out, N);
}

// round 6
// speedup vs baseline: 1.1371x; 1.1371x over previous
#include <cuda_runtime.h>
#include <math.h>

// Problem shape (fixed by dataset): N=100000, H=32, K=15, C_in=C_out=64
#define MAXN 100000
#define NB_H 32
#define KPTS 15
#define CH   64

#define NBLOCKS     296                  // 148 SMs x 2 (co-resident by __launch_bounds__(256,2))
#define NTHREADS    256
#define TOTAL_WARPS (NBLOCKS * 8)

// Scratch (__device__ globals: allocation-free rule)
__device__ float4 g_pts4[MAXN];      // s_pts packed as float4 (w unused)
__device__ float  g_val[MAXN * CH];  // raw kpconv rows for flagged points
__device__ int    g_flag[MAXN];      // 1 if row active
__device__ float  g_sum[CH];
__device__ float  g_sumsq[CH];
// software grid barrier (self-resetting, safe across graph replays)
__device__ int          g_bar_count = 0;
__device__ volatile int g_bar_gen   = 0;

static __host__ __device__ __forceinline__ float kp_extent() {
    return (float)(0.1 * 1.2 / 2.5);
}

static __device__ __forceinline__ void grid_sync() {
    __threadfence();
    __syncthreads();
    if (threadIdx.x == 0) {
        const int gen = g_bar_gen;
        if (atomicAdd(&g_bar_count, 1) == NBLOCKS - 1) {
            g_bar_count = 0;
            __threadfence();
            g_bar_gen = gen + 1;
        } else {
            while (g_bar_gen == gen) { __nanosleep(64); }
        }
    }
    __syncthreads();
}

__global__ void __launch_bounds__(NTHREADS, 2) fused_kernel(
    const float* __restrict__ q_pts,
    const float* __restrict__ s_pts,
    const int*   __restrict__ inds,
    const float* __restrict__ x,
    const float* __restrict__ kp,
    const float* __restrict__ W,    // [K, C, C]
    float* __restrict__ out, int N)
{
    __shared__ float sw[8][KPTS][CH];        // 30 KB, heavy-path staging
    __shared__ float mm[CH], iv[CH], zz[CH]; // phase-C stats

    const int tid   = threadIdx.x;
    const int warp  = tid >> 5;
    const int lane  = tid & 31;
    const int gwarp = blockIdx.x * 8 + warp;
    const unsigned FULL = 0xffffffffu;

    // conservative candidate threshold^2 (broadcast L2 loads, once per thread)
    float thr2;
    {
        float mx2 = 0.0f;
#pragma unroll
        for (int k = 0; k < KPTS; k++) {
            const float a = __ldg(kp + 3*k), b = __ldg(kp + 3*k + 1), c = __ldg(kp + 3*k + 2);
            mx2 = fmaxf(mx2, fmaf(a, a, fmaf(b, b, c * c)));
        }
        const float t = (kp_extent() + sqrtf(mx2)) * 1.0002f + 1e-6f;  // false positives ok
        thr2 = t * t;
    }

    // ---------------- Phase A: pack s_pts, zero flags/sums ----------------
    {
        const int stride = NBLOCKS * NTHREADS;
        for (int i = blockIdx.x * NTHREADS + tid; i < N; i += stride) {
            g_flag[i] = 0;
            g_pts4[i] = make_float4(__ldg(s_pts + 3*i), __ldg(s_pts + 3*i + 1),
                                    __ldg(s_pts + 3*i + 2), 0.0f);
        }
        if (blockIdx.x == 0 && tid < CH) { g_sum[tid] = 0.0f; g_sumsq[tid] = 0.0f; }
    }
    grid_sync();

    // ---------------- Phase B: warp-per-point detect + inline exact heavy path ----------------
    {
        int n = gwarp;
        int idx_next = (n < N) ? __ldg(inds + (long)n * NB_H + lane) : 0;
        for (; n < N; n += TOTAL_WARPS) {
            const int idx = idx_next;
            const int n2 = n + TOTAL_WARPS;
            if (n2 < N) idx_next = __ldg(inds + (long)n2 * NB_H + lane);  // prefetch

            const float qx = __ldg(q_pts + 3*n);
            const float qy = __ldg(q_pts + 3*n + 1);
            const float qz = __ldg(q_pts + 3*n + 2);

            const bool valid = ((unsigned)idx < (unsigned)N);
            float nx = 1e9f, ny = 1e9f, nz = 1e9f;
            if (valid) {
                const float4 p = __ldg(&g_pts4[idx]);
                nx = p.x - qx; ny = p.y - qy; nz = p.z - qz;
            }
            const float r2 = fmaf(nx, nx, fmaf(ny, ny, nz * nz));
            const unsigned mask = __ballot_sync(FULL, valid && (r2 < thr2));
            if (mask == 0) continue;   // ~99.9% of iterations

            // -------- heavy path (rare): exact reference math --------
            const float EXT  = kp_extent();
            const float EXT2 = EXT * EXT;
            const float INVE = 1.0f / EXT;

            float kx[KPTS], ky[KPTS], kz[KPTS];
#pragma unroll
            for (int k = 0; k < KPTS; k++) {
                kx[k] = __ldg(kp + 3*k);
                ky[k] = __ldg(kp + 3*k + 1);
                kz[k] = __ldg(kp + 3*k + 2);
            }

            float acc0[KPTS], acc1[KPTS];
#pragma unroll
            for (int k = 0; k < KPTS; k++) { acc0[k] = 0.0f; acc1[k] = 0.0f; }

            unsigned m = mask;
            while (m) {
                const int hs = __ffs(m) - 1;
                m &= (m - 1);
                const int   sidx = __shfl_sync(FULL, idx, hs);
                const float bx = __shfl_sync(FULL, nx, hs);
                const float by = __shfl_sync(FULL, ny, hs);
                const float bz = __shfl_sync(FULL, nz, hs);
                const float xv0 = __ldg(x + (long)sidx * CH + lane);
                const float xv1 = __ldg(x + (long)sidx * CH + lane + 32);
#pragma unroll
                for (int k = 0; k < KPTS; k++) {
                    const float dx = bx - kx[k];
                    const float dy = by - ky[k];
                    const float dz = bz - kz[k];
                    const float d2 = fmaf(dx, dx, fmaf(dy, dy, dz * dz));
                    if (d2 < EXT2) {
                        const float w = fmaxf(1.0f - sqrtf(d2) * INVE, 0.0f);
                        acc0[k] = fmaf(w, xv0, acc0[k]);
                        acc1[k] = fmaf(w, xv1, acc1[k]);
                    }
                }
            }

            unsigned kmask = 0;
#pragma unroll
            for (int k = 0; k < KPTS; k++) {
                sw[warp][k][lane]      = acc0[k];
                sw[warp][k][lane + 32] = acc1[k];
                if (__ballot_sync(FULL, (acc0[k] != 0.0f) || (acc1[k] != 0.0f)))
                    kmask |= (1u << k);
            }
            __syncwarp();

            float o0 = 0.0f, o1 = 0.0f;
            for (int k = 0; k < KPTS; k++) {
                if (!(kmask & (1u << k))) continue;
                const float* Wk = W + (long)k * CH * CH;
#pragma unroll 8
                for (int c = 0; c < CH; c++) {
                    const float wv = sw[warp][k][c];
                    o0 = fmaf(wv, __ldg(Wk + c * CH + lane),      o0);
                    o1 = fmaf(wv, __ldg(Wk + c * CH + lane + 32), o1);
                }
            }
            __syncwarp();

            g_val[(long)n * CH + lane]      = o0;
            g_val[(long)n * CH + lane + 32] = o1;
            if (lane == 0) g_flag[n] = 1;
            atomicAdd(&g_sum[lane],        o0);
            atomicAdd(&g_sum[lane + 32],   o1);
            atomicAdd(&g_sumsq[lane],      o0 * o0);
            atomicAdd(&g_sumsq[lane + 32], o1 * o1);
        }
    }
    grid_sync();

    // ---------------- Phase C: finalize stats, stream output ----------------
    if (tid < CH) {
        const float invN = 1.0f / (float)N;
        const float mean = g_sum[tid] * invN;
        const float var  = fmaxf(g_sumsq[tid] * invN - mean * mean, 0.0f);
        const float inv  = rsqrtf(var + 1e-5f);
        const float z    = (0.0f - mean) * inv;
        mm[tid] = mean;
        iv[tid] = inv;
        zz[tid] = (z >= 0.0f) ? z : 0.1f * z;
    }
    __syncthreads();

    {
        float4* __restrict__ out4 = reinterpret_cast<float4*>(out);
        const int c4 = (lane & 15) * 4;
        const float4 vz = make_float4(zz[c4], zz[c4 + 1], zz[c4 + 2], zz[c4 + 3]);
        const int ngrp = (N + 31) >> 5;   // 32-row groups

        for (int g = gwarp; g < ngrp; g += TOTAL_WARPS) {
            const int r0 = g * 32;
            const int fn = r0 + lane;
            const int f  = (fn < N) ? g_flag[fn] : 0;   // one coalesced load per warp
            const unsigned hits = __ballot_sync(FULL, f != 0);

            if (hits == 0 && r0 + 32 <= N) {
                // fast path: 32 rows of the constant, 16 STG.128 per lane, no branches
                const long base = (long)g * 512;        // in float4 units (32 rows * 16)
#pragma unroll
                for (int j = 0; j < 16; j++)
                    out4[base + j * 32 + lane] = vz;
            } else {
                // rare / boundary path: per-row scalar handling
                const int rend = min(r0 + 32, N);
                for (int r = r0; r < rend; r++) {
                    const int fr = __shfl_sync(FULL, f, r - r0);
                    float a0, a1;
                    if (fr) {
                        const float v0 = g_val[(long)r * CH + lane];
                        const float v1 = g_val[(long)r * CH + lane + 32];
                        a0 = (v0 - mm[lane])      * iv[lane];
                        a1 = (v1 - mm[lane + 32]) * iv[lane + 32];
                        a0 = (a0 >= 0.0f) ? a0 : 0.1f * a0;
                        a1 = (a1 >= 0.0f) ? a1 : 0.1f * a1;
                    } else {
                        a0 = zz[lane];
                        a1 = zz[lane + 32];
                    }
                    out[(long)r * CH + lane]      = a0;
                    out[(long)r * CH + lane + 32] = a1;
                }
            }
        }
    }
}

// ---------------- launch: ONE kernel ----------------
extern "C" void kernel_launch(void* const* d_in, const int* in_sizes, int n_in,
                              void* d_out, int out_size) {
    const float* q_pts = (const float*)d_in[0];
    const float* s_pts = (const float*)d_in[1];
    const int*   inds  = (const int*)  d_in[2];
    const float* x     = (const float*)d_in[3];
    const float* kp    = (const float*)d_in[4];
    const float* W     = (const float*)d_in[5];
    float* out = (float*)d_out;

    const int N = in_sizes[0] / 3;

    fused_kernel<<<NBLOCKS, NTHREADS>>>(q_pts, s_pts, inds, x, kp, W, out, N);
}

// round 7
// speedup vs baseline: 1.1711x; 1.0299x over previous
#include <cuda_runtime.h>
#include <math.h>

// Problem shape (fixed by dataset): N=100000, H=32, K=15, C_in=C_out=64
#define MAXN 100000
#define NB_H 32
#define KPTS 15
#define CH   64

#define NBLOCKS     592                  // 148 SMs x 4 (co-resident via __launch_bounds__(256,4))
#define NTHREADS    256
#define TOTAL_THREADS (NBLOCKS * NTHREADS)
#define TOTAL_WARPS (NBLOCKS * 8)

// Scratch (__device__ globals: allocation-free rule)
__device__ float4 g_pts4[MAXN];      // s_pts packed as float4 (w unused)
__device__ float  g_val[MAXN * CH];  // raw kpconv rows for flagged points
__device__ int    g_flag[MAXN];      // 1 if candidate row
__device__ float  g_sum[CH];
__device__ float  g_sumsq[CH];
// software grid barrier (self-resetting, safe across graph replays)
__device__ int          g_bar_count = 0;
__device__ volatile int g_bar_gen   = 0;

static __host__ __device__ __forceinline__ float kp_extent() {
    return (float)(0.1 * 1.2 / 2.5);
}

static __device__ __forceinline__ void grid_sync() {
    __threadfence();
    __syncthreads();
    if (threadIdx.x == 0) {
        const int gen = g_bar_gen;
        if (atomicAdd(&g_bar_count, 1) == NBLOCKS - 1) {
            g_bar_count = 0;
            __threadfence();
            g_bar_gen = gen + 1;
        } else {
            while (g_bar_gen == gen) { __nanosleep(32); }
        }
    }
    __syncthreads();
}

__global__ void __launch_bounds__(NTHREADS, 4) fused_kernel(
    const float* __restrict__ q_pts,
    const float* __restrict__ s_pts,
    const int*   __restrict__ inds,
    const float* __restrict__ x,
    const float* __restrict__ kp,
    const float* __restrict__ W,    // [K, C, C]
    float* __restrict__ out, int N)
{
    __shared__ float sw[8][KPTS][CH];        // 30 KB, heavy-phase staging
    __shared__ float mm[CH], iv[CH], zz[CH]; // phase-C stats

    const int tid   = threadIdx.x;
    const int warp  = tid >> 5;
    const int lane  = tid & 31;
    const int gwarp = blockIdx.x * 8 + warp;
    const unsigned FULL = 0xffffffffu;

    // conservative candidate threshold^2 (broadcast L1/L2 loads)
    float thr2;
    {
        float mx2 = 0.0f;
#pragma unroll
        for (int k = 0; k < KPTS; k++) {
            const float a = __ldg(kp + 3*k), b = __ldg(kp + 3*k + 1), c = __ldg(kp + 3*k + 2);
            mx2 = fmaxf(mx2, fmaf(a, a, fmaf(b, b, c * c)));
        }
        const float t = (kp_extent() + sqrtf(mx2)) * 1.0002f + 1e-6f;  // false positives ok
        thr2 = t * t;
    }

    // ---------------- Phase A: pack s_pts, zero flags/sums ----------------
    for (int i = blockIdx.x * NTHREADS + tid; i < N; i += TOTAL_THREADS) {
        g_flag[i] = 0;
        g_pts4[i] = make_float4(__ldg(s_pts + 3*i), __ldg(s_pts + 3*i + 1),
                                __ldg(s_pts + 3*i + 2), 0.0f);
    }
    if (blockIdx.x == 0 && tid < CH) { g_sum[tid] = 0.0f; g_sumsq[tid] = 0.0f; }
    grid_sync();

    // ---------------- Phase B: detect. thread-per-quad, MLP=4, flags only ----------------
    {
        const int nquad = N * (NB_H / 4);   // 800000 int4 quads
        for (int t = blockIdx.x * NTHREADS + tid; t < nquad; t += TOTAL_THREADS) {
            const int n = t >> 3;           // 8 quads per point
            const float qx = __ldg(q_pts + 3*n);
            const float qy = __ldg(q_pts + 3*n + 1);
            const float qz = __ldg(q_pts + 3*n + 2);

            const int4 iv4 = __ldg(reinterpret_cast<const int4*>(inds) + t);

            bool any = false;
            {
                const int id = iv4.x;
                if ((unsigned)id < (unsigned)N) {
                    const float4 p = __ldg(&g_pts4[id]);
                    const float dx = p.x - qx, dy = p.y - qy, dz = p.z - qz;
                    any |= (fmaf(dx, dx, fmaf(dy, dy, dz * dz)) < thr2);
                }
            }
            {
                const int id = iv4.y;
                if ((unsigned)id < (unsigned)N) {
                    const float4 p = __ldg(&g_pts4[id]);
                    const float dx = p.x - qx, dy = p.y - qy, dz = p.z - qz;
                    any |= (fmaf(dx, dx, fmaf(dy, dy, dz * dz)) < thr2);
                }
            }
            {
                const int id = iv4.z;
                if ((unsigned)id < (unsigned)N) {
                    const float4 p = __ldg(&g_pts4[id]);
                    const float dx = p.x - qx, dy = p.y - qy, dz = p.z - qz;
                    any |= (fmaf(dx, dx, fmaf(dy, dy, dz * dz)) < thr2);
                }
            }
            {
                const int id = iv4.w;
                if ((unsigned)id < (unsigned)N) {
                    const float4 p = __ldg(&g_pts4[id]);
                    const float dx = p.x - qx, dy = p.y - qy, dz = p.z - qz;
                    any |= (fmaf(dx, dx, fmaf(dy, dy, dz * dz)) < thr2);
                }
            }
            if (any) g_flag[n] = 1;         // racy same-value store: benign
        }
    }
    grid_sync();

    // ---------------- Phase B2: heavy. ballot-scan flags, exact KPConv per hit ----------------
    {
        const float EXT  = kp_extent();
        const float EXT2 = EXT * EXT;
        const float INVE = 1.0f / EXT;

        const int ngrp = (N + 31) >> 5;
        for (int g = gwarp; g < ngrp; g += TOTAL_WARPS) {
            const int fn = g * 32 + lane;
            const int f = (fn < N) ? g_flag[fn] : 0;
            unsigned hits = __ballot_sync(FULL, f != 0);

            while (hits) {
                const int bit = __ffs(hits) - 1;
                hits &= (hits - 1);
                const int n = g * 32 + bit;

                const float qx = __ldg(q_pts + 3*n);
                const float qy = __ldg(q_pts + 3*n + 1);
                const float qz = __ldg(q_pts + 3*n + 2);

                const int idx = __ldg(inds + (long)n * NB_H + lane);
                const bool valid = ((unsigned)idx < (unsigned)N);
                float nx = 1e9f, ny = 1e9f, nz = 1e9f;
                if (valid) {
                    const float4 p = __ldg(&g_pts4[idx]);
                    nx = p.x - qx; ny = p.y - qy; nz = p.z - qz;
                }
                const float r2 = fmaf(nx, nx, fmaf(ny, ny, nz * nz));
                unsigned mask = __ballot_sync(FULL, valid && (r2 < thr2));

                float acc0[KPTS], acc1[KPTS];
#pragma unroll
                for (int k = 0; k < KPTS; k++) { acc0[k] = 0.0f; acc1[k] = 0.0f; }

                unsigned m = mask;
                while (m) {
                    const int hs = __ffs(m) - 1;
                    m &= (m - 1);
                    const int   sidx = __shfl_sync(FULL, idx, hs);
                    const float bx = __shfl_sync(FULL, nx, hs);
                    const float by = __shfl_sync(FULL, ny, hs);
                    const float bz = __shfl_sync(FULL, nz, hs);
                    const float xv0 = __ldg(x + (long)sidx * CH + lane);
                    const float xv1 = __ldg(x + (long)sidx * CH + lane + 32);
#pragma unroll
                    for (int k = 0; k < KPTS; k++) {
                        const float dx = bx - __ldg(kp + 3*k);
                        const float dy = by - __ldg(kp + 3*k + 1);
                        const float dz = bz - __ldg(kp + 3*k + 2);
                        const float d2 = fmaf(dx, dx, fmaf(dy, dy, dz * dz));
                        if (d2 < EXT2) {
                            const float w = fmaxf(1.0f - sqrtf(d2) * INVE, 0.0f);
                            acc0[k] = fmaf(w, xv0, acc0[k]);
                            acc1[k] = fmaf(w, xv1, acc1[k]);
                        }
                    }
                }

                unsigned kmask = 0;
#pragma unroll
                for (int k = 0; k < KPTS; k++) {
                    sw[warp][k][lane]      = acc0[k];
                    sw[warp][k][lane + 32] = acc1[k];
                    if (__ballot_sync(FULL, (acc0[k] != 0.0f) || (acc1[k] != 0.0f)))
                        kmask |= (1u << k);
                }
                __syncwarp();

                float o0 = 0.0f, o1 = 0.0f;
                for (int k = 0; k < KPTS; k++) {
                    if (!(kmask & (1u << k))) continue;
                    const float* Wk = W + (long)k * CH * CH;
#pragma unroll 8
                    for (int c = 0; c < CH; c++) {
                        const float wv = sw[warp][k][c];
                        o0 = fmaf(wv, __ldg(Wk + c * CH + lane),      o0);
                        o1 = fmaf(wv, __ldg(Wk + c * CH + lane + 32), o1);
                    }
                }
                __syncwarp();

                g_val[(long)n * CH + lane]      = o0;
                g_val[(long)n * CH + lane + 32] = o1;
                atomicAdd(&g_sum[lane],        o0);
                atomicAdd(&g_sum[lane + 32],   o1);
                atomicAdd(&g_sumsq[lane],      o0 * o0);
                atomicAdd(&g_sumsq[lane + 32], o1 * o1);
            }
        }
    }
    grid_sync();

    // ---------------- Phase C: finalize stats, stream output ----------------
    if (tid < CH) {
        const float invN = 1.0f / (float)N;
        const float mean = g_sum[tid] * invN;
        const float var  = fmaxf(g_sumsq[tid] * invN - mean * mean, 0.0f);
        const float inv  = rsqrtf(var + 1e-5f);
        const float z    = (0.0f - mean) * inv;
        mm[tid] = mean;
        iv[tid] = inv;
        zz[tid] = (z >= 0.0f) ? z : 0.1f * z;
    }
    __syncthreads();

    {
        float4* __restrict__ out4 = reinterpret_cast<float4*>(out);
        const int c4 = (lane & 15) * 4;
        const float4 vz = make_float4(zz[c4], zz[c4 + 1], zz[c4 + 2], zz[c4 + 3]);
        const int ngrp = (N + 31) >> 5;   // 32-row groups

        for (int g = gwarp; g < ngrp; g += TOTAL_WARPS) {
            const int r0 = g * 32;
            const int fn = r0 + lane;
            const int f  = (fn < N) ? g_flag[fn] : 0;   // one coalesced load per warp
            const unsigned hits = __ballot_sync(FULL, f != 0);

            if (hits == 0 && r0 + 32 <= N) {
                const long base = (long)g * 512;        // float4 units (32 rows * 16)
#pragma unroll
                for (int j = 0; j < 16; j++)
                    out4[base + j * 32 + lane] = vz;
            } else {
                const int rend = min(r0 + 32, N);
                for (int r = r0; r < rend; r++) {
                    const int fr = __shfl_sync(FULL, f, r - r0);
                    float a0, a1;
                    if (fr) {
                        const float v0 = g_val[(long)r * CH + lane];
                        const float v1 = g_val[(long)r * CH + lane + 32];
                        a0 = (v0 - mm[lane])      * iv[lane];
                        a1 = (v1 - mm[lane + 32]) * iv[lane + 32];
                        a0 = (a0 >= 0.0f) ? a0 : 0.1f * a0;
                        a1 = (a1 >= 0.0f) ? a1 : 0.1f * a1;
                    } else {
                        a0 = zz[lane];
                        a1 = zz[lane + 32];
                    }
                    out[(long)r * CH + lane]      = a0;
                    out[(long)r * CH + lane + 32] = a1;
                }
            }
        }
    }
}

// ---------------- launch: ONE kernel ----------------
extern "C" void kernel_launch(void* const* d_in, const int* in_sizes, int n_in,
                              void* d_out, int out_size) {
    const float* q_pts = (const float*)d_in[0];
    const float* s_pts = (const float*)d_in[1];
    const int*   inds  = (const int*)  d_in[2];
    const float* x     = (const float*)d_in[3];
    const float* kp    = (const float*)d_in[4];
    const float* W     = (const float*)d_in[5];
    float* out = (float*)d_out;

    const int N = in_sizes[0] / 3;

    fused_kernel<<<NBLOCKS, NTHREADS>>>(q_pts, s_pts, inds, x, kp, W, out, N);
}